// round 13
// baseline (speedup 1.0000x reference)
#include <cuda_runtime.h>
#include <cstdint>

// HN=10, ND=40, HF=8 (fixed). A_ENC: agg[j]=sum x[4j-3..4j+2 mod 40].
// A_PRED: agg2[d]=z1[d]+w*(z1[d-1]+z1[d+1]), w=exp(-1/9).
// A_DEC per grid i (m=i%4): m0:s[c]; m1,m2:s[c]+s[c+1]; m3:s[c+1]  (c=i/4, wrap mod 10)
//
// R13 = R12 (champion: cp.async staging, constant weights, stride-41 z1 overlay)
//       + software-pipelined staging: z region at [0,43008), x region at
//       [26112,48640); z chunks k=0..11 (max addr 25792) don't overlap x, so
//       they are issued before agg, overlapping the x-wait and the agg bubble.

typedef unsigned long long u64;
typedef unsigned int u32;

__device__ __forceinline__ u64 pk2(float a, float b) {
    u64 r; asm("mov.b64 %0, {%1, %2};" : "=l"(r) : "f"(a), "f"(b)); return r;
}
__device__ __forceinline__ void upk2(u64 v, float& a, float& b) {
    asm("mov.b64 {%0, %1}, %2;" : "=f"(a), "=f"(b) : "l"(v));
}
__device__ __forceinline__ u64 ffma2(u64 a, u64 b, u64 c) {
    u64 d; asm("fma.rn.f32x2 %0, %1, %2, %3;" : "=l"(d) : "l"(a), "l"(b), "l"(c)); return d;
}
__device__ __forceinline__ u64 add2(u64 a, u64 b) {
    u64 d; asm("add.rn.f32x2 %0, %1, %2;" : "=l"(d) : "l"(a), "l"(b)); return d;
}
__device__ __forceinline__ void cpa16(u32 daddr, const void* g) {
    asm volatile("cp.async.cg.shared.global [%0], [%1], 16;" :: "r"(daddr), "l"(g));
}
__device__ __forceinline__ void cpa_commit() {
    asm volatile("cp.async.commit_group;" ::: "memory");
}
template <int N>
__device__ __forceinline__ void cpa_wait() {
    asm volatile("cp.async.wait_group %0;" :: "n"(N) : "memory");
}

struct CW {
    u64 encW[8][4];   // [g][f2] = (enc_root_w[2f2][g], enc_root_w[2f2+1][g])
    u64 encRW[4];     // enc_rel_w pairs
    u64 encB[4];      // enc_rel_b pairs
    u64 W1[8][4];     // (pred_rel_w + pred_root_w) pairs
    u64 W2[8][4];     // (exp(-1/9) * pred_rel_w) pairs
    u64 predB[4];     // pred_rel_b pairs
    float drw[8];     // dec_rel_w
    float dec2[2];    // dec_rel_b, dec_root_w
};
__constant__ CW c_w;
__device__ CW g_stage;

__global__ void prep_kernel(const float* __restrict__ erw, const float* __restrict__ erb,
                            const float* __restrict__ erow,
                            const float* __restrict__ prw, const float* __restrict__ prb,
                            const float* __restrict__ prow,
                            const float* __restrict__ drw, const float* __restrict__ drb,
                            const float* __restrict__ droot) {
    const int t = threadIdx.x;
    const float wE = expf(-1.0f / 9.0f);
    if (t < 32) {
        const int g = t & 7, f2 = t >> 3;
        const int i0 = (2 * f2) * 8 + g;
        const int i1 = (2 * f2 + 1) * 8 + g;
        g_stage.encW[g][f2] = pk2(erow[i0], erow[i1]);
        g_stage.W1[g][f2]   = pk2(prw[i0] + prow[i0], prw[i1] + prow[i1]);
        g_stage.W2[g][f2]   = pk2(wE * prw[i0], wE * prw[i1]);
    }
    if (t < 4) {
        g_stage.encRW[t] = pk2(erw[2 * t], erw[2 * t + 1]);
        g_stage.encB[t]  = pk2(erb[2 * t], erb[2 * t + 1]);
        g_stage.predB[t] = pk2(prb[2 * t], prb[2 * t + 1]);
    }
    if (t < 8) g_stage.drw[t] = drw[t];
    if (t == 0) { g_stage.dec2[0] = drb[0]; g_stage.dec2[1] = droot[0]; }
}

// Shared map (bytes): z [0,43008) as [128][21] float4 (z1 overlay u64 stride 41);
// x [26112,48640) as [128][11] float4 (dead after agg; z-upper k>=12 and ss may
// overwrite); ss [43008,48640) float[128][11] (written in stage B).
// z-lower (k=0..11) max byte = 25792 < 26112 -> no overlap with x.  Total 48640B
// -> 4 blocks/SM at <=128 regs (16 warps).
#define ZROW 21
#define XBASE_F4 1632                       /* 26112 / 16 */
#define SS_F4    2688                       /* 43008 / 16 */
#define SMEM_BYTES (128 * ZROW * 16 + 128 * 11 * 4)

__global__ __launch_bounds__(128, 4)
void gnn_kernel(const float* __restrict__ x, const float* __restrict__ z,
                const float* __restrict__ y, float* __restrict__ out) {
    extern __shared__ float4 sm4[];
    float4* zbuf = sm4;                     // [128][21] float4
    float4* xbuf = sm4 + XBASE_F4;          // [128][11] float4
    float*  ss   = (float*)(sm4 + SS_F4);   // [128][11] float
    u64*    z1b  = (u64*)sm4;               // z1 overlay; row stride 41 u64

    const int t = threadIdx.x;
    const int blk = blockIdx.x;
    const u32 sbase = (u32)__cvta_generic_to_shared(sm4);

    const float4* xg = (const float4*)x + (long long)blk * 1280;
    const float4* zg = (const float4*)z + (long long)blk * 2560;

    // ---- Pipelined staging: x (group0), then z-lower (group1) back-to-back ----
#pragma unroll
    for (int k = 0; k < 10; k++) {
        const int i4 = t + k * 128;
        cpa16(sbase + (XBASE_F4 + (i4 / 10) * 11 + (i4 % 10)) * 16, xg + i4);
    }
    cpa_commit();                            // group: x
#pragma unroll
    for (int k = 0; k < 12; k++) {           // z-lower: stays below byte 26112
        const int i4 = t + k * 128;
        cpa16(sbase + ((i4 / 20) * ZROW + (i4 % 20)) * 16, zg + i4);
    }
    cpa_commit();                            // group: z-lower

    cpa_wait<1>();                           // x complete (z-lower may stream on)
    __syncthreads();

    // ---- Encoder ring aggregation (x reads; z-lower streaming concurrently) ----
    float t1[10], t2[10];
#pragma unroll
    for (int c = 0; c < 10; c++) {
        const float4 v = xbuf[t * 11 + c];
        t1[c] = v.y + v.z + v.w;
        t2[c] = v.x + v.y + v.z;
    }
    float agg[10];
#pragma unroll
    for (int j = 0; j < 10; j++) agg[j] = t1[(j + 9) % 10] + t2[j];
    __syncthreads();                         // x reads done; x region reusable

    // ---- z-upper (k=12..19; may overwrite the dead x region) ----
#pragma unroll
    for (int k = 12; k < 20; k++) {
        const int i4 = t + k * 128;
        cpa16(sbase + ((i4 / 20) * ZROW + (i4 % 20)) * 16, zg + i4);
    }
    cpa_commit();                            // group: z-upper
    cpa_wait<0>();                           // all z complete
    __syncthreads();

    const float4* row = zbuf + t * ZROW;

    // ======== Stage A: zz[4j+f2] = (z1[j][2f2], z1[j][2f2+1]) pre-relu ========
    u64 zz[40];
#pragma unroll
    for (int j = 0; j < 10; j++) {
        const u64 ab = pk2(agg[j], agg[j]);
#pragma unroll
        for (int f2 = 0; f2 < 4; f2++)
            zz[4 * j + f2] = ffma2(ab, c_w.encRW[f2], c_w.encB[f2]);
    }
#pragma unroll 1
    for (int gh = 0; gh < 2; gh++) {
        u64 w[4][4];
#pragma unroll
        for (int gw = 0; gw < 4; gw++)
#pragma unroll
            for (int f2 = 0; f2 < 4; f2++) w[gw][f2] = c_w.encW[4 * gh + gw][f2];
#pragma unroll
        for (int j = 0; j < 10; j++) {
            const float4 zv = row[2 * j + gh];
            const float zsc[4] = {zv.x, zv.y, zv.z, zv.w};
#pragma unroll
            for (int gw = 0; gw < 4; gw++) {
                const u64 zb = pk2(zsc[gw], zsc[gw]);
#pragma unroll
                for (int f2 = 0; f2 < 4; f2++)
                    zz[4 * j + f2] = ffma2(zb, w[gw][f2], zz[4 * j + f2]);
            }
        }
    }
    __syncthreads();   // every thread done reading z before z1 overlay writes

    // relu + store z1 as packed b64 pairs at stride 41 (conflict-free)
    u64* myz1 = z1b + t * 41;
#pragma unroll
    for (int i = 0; i < 40; i++) {
        float a, b; upk2(zz[i], a, b);
        myz1[i] = pk2(fmaxf(a, 0.0f), fmaxf(b, 0.0f));
    }

    // ======== Stage B: z2[d] = relu(z1[d]@W1^T + (z1[d-1]+z1[d+1])@W2^T + prb) ====
    //          s[d] = z2[d]·drw
#pragma unroll
    for (int dh = 0; dh < 2; dh++) {
        u64 acc[20];
#pragma unroll
        for (int d5 = 0; d5 < 5; d5++)
#pragma unroll
            for (int f2 = 0; f2 < 4; f2++) acc[4 * d5 + f2] = c_w.predB[f2];

#pragma unroll 1
        for (int p = 0; p < 4; p++) {       // g-pair (2p, 2p+1)
            u64 w1lo[4], w1hi[4], w2lo[4], w2hi[4];
#pragma unroll
            for (int f2 = 0; f2 < 4; f2++) {
                w1lo[f2] = c_w.W1[2 * p][f2];
                w1hi[f2] = c_w.W1[2 * p + 1][f2];
                w2lo[f2] = c_w.W2[2 * p][f2];
                w2hi[f2] = c_w.W2[2 * p + 1][f2];
            }
            u64 zr[7];
#pragma unroll
            for (int k = 0; k < 7; k++)
                zr[k] = myz1[4 * ((dh * 5 + k + 9) % 10) + p];
#pragma unroll
            for (int d5 = 0; d5 < 5; d5++) {
                const u64 zd = zr[d5 + 1];
                const u64 up = add2(zr[d5], zr[d5 + 2]);
                float zl, zh, ul, uh;
                upk2(zd, zl, zh); upk2(up, ul, uh);
                const u64 bzl = pk2(zl, zl), bzh = pk2(zh, zh);
                const u64 bul = pk2(ul, ul), buh = pk2(uh, uh);
#pragma unroll
                for (int f2 = 0; f2 < 4; f2++) {
                    u64 a = acc[4 * d5 + f2];
                    a = ffma2(bzl, w1lo[f2], a);
                    a = ffma2(bzh, w1hi[f2], a);
                    a = ffma2(bul, w2lo[f2], a);
                    a = ffma2(buh, w2hi[f2], a);
                    acc[4 * d5 + f2] = a;
                }
            }
        }
        // relu + dot with dec_rel_w -> s[d]
#pragma unroll
        for (int d5 = 0; d5 < 5; d5++) {
            float f0, f1, f2v, f3, f4v, f5, f6, f7;
            upk2(acc[4 * d5 + 0], f0, f1);
            upk2(acc[4 * d5 + 1], f2v, f3);
            upk2(acc[4 * d5 + 2], f4v, f5);
            upk2(acc[4 * d5 + 3], f6, f7);
            const float sd = fmaxf(f0, 0.0f) * c_w.drw[0] + fmaxf(f1, 0.0f) * c_w.drw[1]
                           + fmaxf(f2v, 0.0f) * c_w.drw[2] + fmaxf(f3, 0.0f) * c_w.drw[3]
                           + fmaxf(f4v, 0.0f) * c_w.drw[4] + fmaxf(f5, 0.0f) * c_w.drw[5]
                           + fmaxf(f6, 0.0f) * c_w.drw[6] + fmaxf(f7, 0.0f) * c_w.drw[7];
            ss[t * 11 + dh * 5 + d5] = sd;
        }
    }
    __syncthreads();

    // ---- Decoder/output: fully coalesced float4 y-load + out-store ----
    const float drbv   = c_w.dec2[0];
    const float drootv = c_w.dec2[1];
    const float4* yg = (const float4*)y + (long long)blk * 1280;
    float4* og = (float4*)out + (long long)blk * 1280;
#pragma unroll
    for (int p = 0; p < 10; p++) {
        const int n4 = t + p * 128;
        const int bl = n4 / 10, c = n4 % 10;
        const float sa = ss[bl * 11 + c];
        const float sb = ss[bl * 11 + ((c == 9) ? 0 : c + 1)];
        const float4 yv = yg[n4];
        float4 o;
        o.x = sa + drbv + yv.x * drootv;          // m=0
        o.y = sa + sb + drbv + yv.y * drootv;     // m=1
        o.z = sa + sb + drbv + yv.z * drootv;     // m=2
        o.w = sb + drbv + yv.w * drootv;          // m=3
        og[n4] = o;
    }
}

extern "C" void kernel_launch(void* const* d_in, const int* in_sizes, int n_in,
                              void* d_out, int out_size) {
    const float* x     = (const float*)d_in[0];
    const float* z     = (const float*)d_in[1];
    const float* y     = (const float*)d_in[2];
    const float* erw   = (const float*)d_in[3];
    const float* erb   = (const float*)d_in[4];
    const float* erow  = (const float*)d_in[5];
    const float* prw   = (const float*)d_in[6];
    const float* prb   = (const float*)d_in[7];
    const float* prow  = (const float*)d_in[8];
    const float* drw   = (const float*)d_in[9];
    const float* drb   = (const float*)d_in[10];
    const float* droot = (const float*)d_in[11];

    const int B = in_sizes[0] / 40;       // 524288
    const int blocks = B / 128;           // 4096

    cudaFuncSetAttribute(gnn_kernel, cudaFuncAttributeMaxDynamicSharedMemorySize, SMEM_BYTES);

    prep_kernel<<<1, 32>>>(erw, erb, erow, prw, prb, prow, drw, drb, droot);

    void* stage_ptr = nullptr;
    cudaGetSymbolAddress(&stage_ptr, g_stage);
    cudaMemcpyToSymbolAsync(c_w, stage_ptr, sizeof(CW), 0, cudaMemcpyDeviceToDevice);

    gnn_kernel<<<blocks, 128, SMEM_BYTES>>>(x, z, y, (float*)d_out);
}